// round 1
// baseline (speedup 1.0000x reference)
#include <cuda_runtime.h>
#include <math_constants.h>

#define BETA 100.0f

// Scratch for per-(node,col) softmax denominator. N*d = 50000*64 = 3.2M floats.
// Static __device__ array (no allocation allowed in kernel_launch).
#define SEG_CAP 3400000
__device__ float g_denom[SEG_CAP];

// ---------- monotonic float<->uint encoding for atomicMax ----------
__device__ __forceinline__ unsigned enc_f(float f) {
    unsigned u = __float_as_uint(f);
    return (u & 0x80000000u) ? ~u : (u | 0x80000000u);
}
__device__ __forceinline__ float dec_f(unsigned u) {
    if (u == 0u) return -CUDART_INF_F;                 // untouched segment
    return __uint_as_float((u & 0x80000000u) ? (u & 0x7FFFFFFFu) : ~u);
}

// ---------- kernels ----------
__global__ void k_init(unsigned* __restrict__ mv, int seg) {
    int i = blockIdx.x * blockDim.x + threadIdx.x;
    if (i < seg) { mv[i] = 0u; g_denom[i] = 0.0f; }
}

// one thread per (edge, col) element: fully coalesced loads and contiguous
// per-lane atomic addresses within each 64-wide row.
template <int D>
__global__ void k_max(const float* __restrict__ M, const int* __restrict__ dest,
                      unsigned* __restrict__ mv, int total) {
    int i = blockIdx.x * blockDim.x + threadIdx.x;
    if (i >= total) return;
    int e = i / D;
    int c = i - e * D;
    float m = M[i];
    int dst = __ldg(dest + e);
    atomicMax(mv + dst * D + c, enc_f(m));
}

__global__ void k_dec(unsigned* __restrict__ mv, int seg) {
    int i = blockIdx.x * blockDim.x + threadIdx.x;
    if (i < seg) mv[i] = __float_as_uint(dec_f(mv[i]));
}

template <int D>
__global__ void k_denom(const float* __restrict__ M, const int* __restrict__ dest,
                        const float* __restrict__ mv, int total) {
    int i = blockIdx.x * blockDim.x + threadIdx.x;
    if (i >= total) return;
    int e = i / D;
    int c = i - e * D;
    int dst = __ldg(dest + e);
    float m  = M[i];
    float mx = __ldg(mv + dst * D + c);          // L2-hot gather (12.8 MB, 25x reuse)
    float z  = __expf(BETA * (m - mx));
    atomicAdd(&g_denom[dst * D + c], z);
}

template <int D>  // D divisible by 4; one float4 per thread
__global__ void k_w(const float* __restrict__ M, const int* __restrict__ dest,
                    const float* __restrict__ mv, float* __restrict__ w, int total4) {
    int i = blockIdx.x * blockDim.x + threadIdx.x;
    if (i >= total4) return;
    constexpr int D4 = D / 4;
    int e  = i / D4;
    int c4 = i - e * D4;
    int dst = __ldg(dest + e);
    float4 m  = reinterpret_cast<const float4*>(M)[i];
    float4 mx = reinterpret_cast<const float4*>(mv)[dst * D4 + c4];
    const float4* dn4 = reinterpret_cast<const float4*>(g_denom);
    float4 dn = dn4[dst * D4 + c4];
    float4 o;
    o.x = __fdividef(__expf(BETA * (m.x - mx.x)), dn.x);
    o.y = __fdividef(__expf(BETA * (m.y - mx.y)), dn.y);
    o.z = __fdividef(__expf(BETA * (m.z - mx.z)), dn.z);
    o.w = __fdividef(__expf(BETA * (m.w - mx.w)), dn.w);
    reinterpret_cast<float4*>(w)[i] = o;
}

// -------- generic (runtime d) fallbacks, in case d != 64 --------
__global__ void k_max_g(const float* __restrict__ M, const int* __restrict__ dest,
                        unsigned* __restrict__ mv, int total, int d) {
    int i = blockIdx.x * blockDim.x + threadIdx.x;
    if (i >= total) return;
    int e = i / d, c = i - e * d;
    atomicMax(mv + __ldg(dest + e) * d + c, enc_f(M[i]));
}
__global__ void k_denom_g(const float* __restrict__ M, const int* __restrict__ dest,
                          const float* __restrict__ mv, int total, int d) {
    int i = blockIdx.x * blockDim.x + threadIdx.x;
    if (i >= total) return;
    int e = i / d, c = i - e * d;
    int o = __ldg(dest + e) * d + c;
    atomicAdd(&g_denom[o], __expf(BETA * (M[i] - __ldg(mv + o))));
}
__global__ void k_w_g(const float* __restrict__ M, const int* __restrict__ dest,
                      const float* __restrict__ mv, float* __restrict__ w, int total, int d) {
    int i = blockIdx.x * blockDim.x + threadIdx.x;
    if (i >= total) return;
    int e = i / d, c = i - e * d;
    int o = __ldg(dest + e) * d + c;
    w[i] = __fdividef(__expf(BETA * (M[i] - __ldg(mv + o))), g_denom[o]);
}

extern "C" void kernel_launch(void* const* d_in, const int* in_sizes, int n_in,
                              void* d_out, int out_size) {
    const float* M    = (const float*)d_in[0];
    const int*   dest = (const int*)d_in[1];

    const int E = in_sizes[1];
    const int d = in_sizes[0] / E;          // 64
    const int N = out_size / d - E;         // 50000 (avoids reading device scalar)

    const int seg    = N * d;               // 3.2M
    const int total  = E * d;               // 80M
    const int total4 = total / 4;

    unsigned* mv_u = (unsigned*)d_out;      // M_v region doubles as encoded-max scratch
    float*    mv_f = (float*)d_out;
    float*    w    = (float*)d_out + (size_t)N * d;

    const int T = 256;
    k_init<<<(seg + T - 1) / T, T>>>(mv_u, seg);

    if (d == 64) {
        k_max<64><<<(total + T - 1) / T, T>>>(M, dest, mv_u, total);
        k_dec<<<(seg + T - 1) / T, T>>>(mv_u, seg);
        k_denom<64><<<(total + T - 1) / T, T>>>(M, dest, mv_f, total);
        k_w<64><<<(total4 + T - 1) / T, T>>>(M, dest, mv_f, w, total4);
    } else {
        k_max_g<<<(total + T - 1) / T, T>>>(M, dest, mv_u, total, d);
        k_dec<<<(seg + T - 1) / T, T>>>(mv_u, seg);
        k_denom_g<<<(total + T - 1) / T, T>>>(M, dest, mv_f, total, d);
        k_w_g<<<(total + T - 1) / T, T>>>(M, dest, mv_f, w, total, d);
    }
}

// round 4
// speedup vs baseline: 2.4694x; 2.4694x over previous
#include <cuda_runtime.h>
#include <math_constants.h>

#define BETA 100.0f

// ---------------- static scratch (no allocations allowed) ----------------
#define NCAP 65536
#define ECAP 2097152
__device__ int g_cnt[NCAP + 1];   // histogram / scatter cursor
__device__ int g_off[NCAP + 1];   // exclusive offsets, g_off[N] = E
__device__ int g_eid[ECAP];       // edge ids bucketed by dest
__device__ float g_denom[4194304]; // fallback path scratch

// ==================== CSR build ====================
__global__ void k_zero_cnt(int N) {
    int i = blockIdx.x * blockDim.x + threadIdx.x;
    if (i <= N) g_cnt[i] = 0;
}

__global__ void k_hist(const int* __restrict__ dest, int E) {
    int i = blockIdx.x * blockDim.x + threadIdx.x;
    if (i < E) atomicAdd(&g_cnt[dest[i]], 1);
}

// single-block exclusive scan of g_cnt[0..N) -> g_off; resets g_cnt to 0
__global__ void k_scan(int N) {
    __shared__ int warp_sums[32];
    __shared__ int carry_s;
    if (threadIdx.x == 0) carry_s = 0;
    __syncthreads();
    int lane = threadIdx.x & 31, wid = threadIdx.x >> 5;
    for (int base = 0; base < N; base += 1024) {
        int i = base + (int)threadIdx.x;
        int v = (i < N) ? g_cnt[i] : 0;
        int x = v;
        #pragma unroll
        for (int o = 1; o < 32; o <<= 1) {
            int t = __shfl_up_sync(0xFFFFFFFFu, x, o);
            if (lane >= o) x += t;
        }
        if (lane == 31) warp_sums[wid] = x;
        __syncthreads();
        if (threadIdx.x < 32) {
            int y = warp_sums[threadIdx.x];
            #pragma unroll
            for (int o = 1; o < 32; o <<= 1) {
                int t = __shfl_up_sync(0xFFFFFFFFu, y, o);
                if ((int)threadIdx.x >= o) y += t;
            }
            warp_sums[threadIdx.x] = y;
        }
        __syncthreads();
        int warpPrev = (wid > 0) ? warp_sums[wid - 1] : 0;
        int excl = x + warpPrev - v;
        int carry = carry_s;
        if (i < N) { g_off[i] = carry + excl; g_cnt[i] = 0; }
        int blockTotal = warp_sums[31];
        __syncthreads();
        if (threadIdx.x == 0) carry_s = carry + blockTotal;
        __syncthreads();
    }
    if (threadIdx.x == 0) g_off[N] = carry_s;
}

__global__ void k_scatter(const int* __restrict__ dest, int E) {
    int i = blockIdx.x * blockDim.x + threadIdx.x;
    if (i >= E) return;
    int d = dest[i];
    int pos = g_off[d] + atomicAdd(&g_cnt[d], 1);
    g_eid[pos] = i;
}

// ==================== per-node fused kernel (d == 64) ====================
// one warp per node; 2 columns per lane (float2).
// Pass A: online softmax (running max + rescaled sum). Pass B: write w.
__global__ void k_node64(const float* __restrict__ M, float* __restrict__ mv,
                         float* __restrict__ w, int N) {
    int gw = (blockIdx.x * blockDim.x + threadIdx.x) >> 5;
    if (gw >= N) return;
    int lane = threadIdx.x & 31;
    int s0 = g_off[gw], s1 = g_off[gw + 1];

    const float2* M2 = (const float2*)M;
    float2 mx = make_float2(-CUDART_INF_F, -CUDART_INF_F);
    float2 s  = make_float2(0.f, 0.f);

    // pass A: fused max + denom (online rescale)
    for (int j = s0; j < s1; j += 32) {
        int cnt = min(32, s1 - j);
        int eid = (j + lane < s1) ? g_eid[j + lane] : 0;
        for (int k = 0; k < cnt; k++) {
            int e = __shfl_sync(0xFFFFFFFFu, eid, k);
            float2 v = M2[(size_t)e * 32 + lane];
            float nx = fmaxf(mx.x, v.x);
            float ny = fmaxf(mx.y, v.y);
            s.x = s.x * __expf(BETA * (mx.x - nx)) + __expf(BETA * (v.x - nx));
            s.y = s.y * __expf(BETA * (mx.y - ny)) + __expf(BETA * (v.y - ny));
            mx.x = nx; mx.y = ny;
        }
    }
    ((float2*)mv)[(size_t)gw * 32 + lane] = mx;
    float2 inv = make_float2(__fdividef(1.f, s.x), __fdividef(1.f, s.y));

    // pass B: write w (M rows L1-hot from pass A)
    float2* W2 = (float2*)w;
    for (int j = s0; j < s1; j += 32) {
        int cnt = min(32, s1 - j);
        int eid = (j + lane < s1) ? g_eid[j + lane] : 0;
        for (int k = 0; k < cnt; k++) {
            int e = __shfl_sync(0xFFFFFFFFu, eid, k);
            float2 v = M2[(size_t)e * 32 + lane];
            float2 o;
            o.x = __expf(BETA * (v.x - mx.x)) * inv.x;
            o.y = __expf(BETA * (v.y - mx.y)) * inv.y;
            W2[(size_t)e * 32 + lane] = o;
        }
    }
}

// ==================== generic atomic fallback (d != 64 or over caps) ====================
__device__ __forceinline__ unsigned enc_f(float f) {
    unsigned u = __float_as_uint(f);
    return (u & 0x80000000u) ? ~u : (u | 0x80000000u);
}
__device__ __forceinline__ float dec_f(unsigned u) {
    if (u == 0u) return -CUDART_INF_F;
    return __uint_as_float((u & 0x80000000u) ? (u & 0x7FFFFFFFu) : ~u);
}
__global__ void k_init_g(unsigned* __restrict__ mvv, int seg) {
    int i = blockIdx.x * blockDim.x + threadIdx.x;
    if (i < seg) { mvv[i] = 0u; g_denom[i] = 0.0f; }
}
__global__ void k_max_g(const float* __restrict__ M, const int* __restrict__ dest,
                        unsigned* __restrict__ mvv, int total, int d) {
    int i = blockIdx.x * blockDim.x + threadIdx.x;
    if (i >= total) return;
    int e = i / d, c = i - e * d;
    atomicMax(mvv + __ldg(dest + e) * d + c, enc_f(M[i]));
}
__global__ void k_dec_g(unsigned* __restrict__ mvv, int seg) {
    int i = blockIdx.x * blockDim.x + threadIdx.x;
    if (i < seg) mvv[i] = __float_as_uint(dec_f(mvv[i]));
}
__global__ void k_denom_g(const float* __restrict__ M, const int* __restrict__ dest,
                          const float* __restrict__ mvf, int total, int d) {
    int i = blockIdx.x * blockDim.x + threadIdx.x;
    if (i >= total) return;
    int e = i / d, c = i - e * d;
    int o = __ldg(dest + e) * d + c;
    atomicAdd(&g_denom[o], __expf(BETA * (M[i] - __ldg(mvf + o))));
}
__global__ void k_w_g(const float* __restrict__ M, const int* __restrict__ dest,
                      const float* __restrict__ mvf, float* __restrict__ w, int total, int d) {
    int i = blockIdx.x * blockDim.x + threadIdx.x;
    if (i >= total) return;
    int e = i / d, c = i - e * d;
    int o = __ldg(dest + e) * d + c;
    w[i] = __fdividef(__expf(BETA * (M[i] - __ldg(mvf + o))), g_denom[o]);
}

extern "C" void kernel_launch(void* const* d_in, const int* in_sizes, int n_in,
                              void* d_out, int out_size) {
    const float* M    = (const float*)d_in[0];
    const int*   dest = (const int*)d_in[1];

    const int E = in_sizes[1];
    const int d = in_sizes[0] / E;     // 64
    const int N = out_size / d - E;    // 50000

    float* mv = (float*)d_out;
    float* w  = (float*)d_out + (size_t)N * d;

    const int T = 256;

    if (d == 64 && N <= NCAP && E <= ECAP) {
        k_zero_cnt<<<(N + T) / T, T>>>(N);
        k_hist<<<(E + T - 1) / T, T>>>(dest, E);
        k_scan<<<1, 1024>>>(N);
        k_scatter<<<(E + T - 1) / T, T>>>(dest, E);
        int threads = N * 32;
        k_node64<<<(threads + T - 1) / T, T>>>(M, mv, w, N);
    } else {
        const int seg = N * d, total = E * d;
        unsigned* mv_u = (unsigned*)d_out;
        k_init_g<<<(seg + T - 1) / T, T>>>(mv_u, seg);
        k_max_g<<<(total + T - 1) / T, T>>>(M, dest, mv_u, total, d);
        k_dec_g<<<(seg + T - 1) / T, T>>>(mv_u, seg);
        k_denom_g<<<(total + T - 1) / T, T>>>(M, dest, mv, total, d);
        k_w_g<<<(total + T - 1) / T, T>>>(M, dest, mv, w, total, d);
    }
}

// round 5
// speedup vs baseline: 2.4758x; 1.0026x over previous
#include <cuda_runtime.h>
#include <math_constants.h>

#define BETA 100.0f

// ---------------- static scratch (no allocations allowed) ----------------
#define NCAP 65536
#define ECAP 2097152
__device__ int g_cnt[NCAP + 1];   // histogram / scatter cursor
__device__ int g_off[NCAP + 1];   // exclusive offsets, g_off[N] = E
__device__ int g_eid[ECAP];       // edge ids bucketed by dest
__device__ float g_denom[4194304]; // fallback path scratch

// ==================== CSR build ====================
__global__ void k_zero_cnt(int N) {
    int i = blockIdx.x * blockDim.x + threadIdx.x;
    if (i <= N) g_cnt[i] = 0;
}

__global__ void k_hist(const int* __restrict__ dest, int E) {
    int i = blockIdx.x * blockDim.x + threadIdx.x;
    if (i < E) atomicAdd(&g_cnt[dest[i]], 1);
}

// single-block exclusive scan of g_cnt[0..N) -> g_off; resets g_cnt to 0
__global__ void k_scan(int N) {
    __shared__ int warp_sums[32];
    __shared__ int carry_s;
    if (threadIdx.x == 0) carry_s = 0;
    __syncthreads();
    int lane = threadIdx.x & 31, wid = threadIdx.x >> 5;
    for (int base = 0; base < N; base += 1024) {
        int i = base + (int)threadIdx.x;
        int v = (i < N) ? g_cnt[i] : 0;
        int x = v;
        #pragma unroll
        for (int o = 1; o < 32; o <<= 1) {
            int t = __shfl_up_sync(0xFFFFFFFFu, x, o);
            if (lane >= o) x += t;
        }
        if (lane == 31) warp_sums[wid] = x;
        __syncthreads();
        if (threadIdx.x < 32) {
            int y = warp_sums[threadIdx.x];
            #pragma unroll
            for (int o = 1; o < 32; o <<= 1) {
                int t = __shfl_up_sync(0xFFFFFFFFu, y, o);
                if ((int)threadIdx.x >= o) y += t;
            }
            warp_sums[threadIdx.x] = y;
        }
        __syncthreads();
        int warpPrev = (wid > 0) ? warp_sums[wid - 1] : 0;
        int excl = x + warpPrev - v;
        int carry = carry_s;
        if (i < N) { g_off[i] = carry + excl; g_cnt[i] = 0; }
        int blockTotal = warp_sums[31];
        __syncthreads();
        if (threadIdx.x == 0) carry_s = carry + blockTotal;
        __syncthreads();
    }
    if (threadIdx.x == 0) g_off[N] = carry_s;
}

__global__ void k_scatter(const int* __restrict__ dest, int E) {
    int i = blockIdx.x * blockDim.x + threadIdx.x;
    if (i >= E) return;
    int d = dest[i];
    int pos = g_off[d] + atomicAdd(&g_cnt[d], 1);
    g_eid[pos] = i;
}

// ==================== per-node fused kernel (d == 64) ====================
// one warp per node; 2 columns per lane (float2).
// Pass A: online softmax (running max + rescaled sum). Pass B: write w.
__global__ void k_node64(const float* __restrict__ M, float* __restrict__ mv,
                         float* __restrict__ w, int N) {
    int gw = (blockIdx.x * blockDim.x + threadIdx.x) >> 5;
    if (gw >= N) return;
    int lane = threadIdx.x & 31;
    int s0 = g_off[gw], s1 = g_off[gw + 1];

    const float2* M2 = (const float2*)M;
    float2 mx = make_float2(-CUDART_INF_F, -CUDART_INF_F);
    float2 s  = make_float2(0.f, 0.f);

    // pass A: fused max + denom (online rescale)
    for (int j = s0; j < s1; j += 32) {
        int cnt = min(32, s1 - j);
        int eid = (j + lane < s1) ? g_eid[j + lane] : 0;
        for (int k = 0; k < cnt; k++) {
            int e = __shfl_sync(0xFFFFFFFFu, eid, k);
            float2 v = M2[(size_t)e * 32 + lane];
            float nx = fmaxf(mx.x, v.x);
            float ny = fmaxf(mx.y, v.y);
            s.x = s.x * __expf(BETA * (mx.x - nx)) + __expf(BETA * (v.x - nx));
            s.y = s.y * __expf(BETA * (mx.y - ny)) + __expf(BETA * (v.y - ny));
            mx.x = nx; mx.y = ny;
        }
    }
    ((float2*)mv)[(size_t)gw * 32 + lane] = mx;
    float2 inv = make_float2(__fdividef(1.f, s.x), __fdividef(1.f, s.y));

    // pass B: write w (M rows L1-hot from pass A)
    float2* W2 = (float2*)w;
    for (int j = s0; j < s1; j += 32) {
        int cnt = min(32, s1 - j);
        int eid = (j + lane < s1) ? g_eid[j + lane] : 0;
        for (int k = 0; k < cnt; k++) {
            int e = __shfl_sync(0xFFFFFFFFu, eid, k);
            float2 v = M2[(size_t)e * 32 + lane];
            float2 o;
            o.x = __expf(BETA * (v.x - mx.x)) * inv.x;
            o.y = __expf(BETA * (v.y - mx.y)) * inv.y;
            W2[(size_t)e * 32 + lane] = o;
        }
    }
}

// ==================== generic atomic fallback (d != 64 or over caps) ====================
__device__ __forceinline__ unsigned enc_f(float f) {
    unsigned u = __float_as_uint(f);
    return (u & 0x80000000u) ? ~u : (u | 0x80000000u);
}
__device__ __forceinline__ float dec_f(unsigned u) {
    if (u == 0u) return -CUDART_INF_F;
    return __uint_as_float((u & 0x80000000u) ? (u & 0x7FFFFFFFu) : ~u);
}
__global__ void k_init_g(unsigned* __restrict__ mvv, int seg) {
    int i = blockIdx.x * blockDim.x + threadIdx.x;
    if (i < seg) { mvv[i] = 0u; g_denom[i] = 0.0f; }
}
__global__ void k_max_g(const float* __restrict__ M, const int* __restrict__ dest,
                        unsigned* __restrict__ mvv, int total, int d) {
    int i = blockIdx.x * blockDim.x + threadIdx.x;
    if (i >= total) return;
    int e = i / d, c = i - e * d;
    atomicMax(mvv + __ldg(dest + e) * d + c, enc_f(M[i]));
}
__global__ void k_dec_g(unsigned* __restrict__ mvv, int seg) {
    int i = blockIdx.x * blockDim.x + threadIdx.x;
    if (i < seg) mvv[i] = __float_as_uint(dec_f(mvv[i]));
}
__global__ void k_denom_g(const float* __restrict__ M, const int* __restrict__ dest,
                          const float* __restrict__ mvf, int total, int d) {
    int i = blockIdx.x * blockDim.x + threadIdx.x;
    if (i >= total) return;
    int e = i / d, c = i - e * d;
    int o = __ldg(dest + e) * d + c;
    atomicAdd(&g_denom[o], __expf(BETA * (M[i] - __ldg(mvf + o))));
}
__global__ void k_w_g(const float* __restrict__ M, const int* __restrict__ dest,
                      const float* __restrict__ mvf, float* __restrict__ w, int total, int d) {
    int i = blockIdx.x * blockDim.x + threadIdx.x;
    if (i >= total) return;
    int e = i / d, c = i - e * d;
    int o = __ldg(dest + e) * d + c;
    w[i] = __fdividef(__expf(BETA * (M[i] - __ldg(mvf + o))), g_denom[o]);
}

extern "C" void kernel_launch(void* const* d_in, const int* in_sizes, int n_in,
                              void* d_out, int out_size) {
    const float* M    = (const float*)d_in[0];
    const int*   dest = (const int*)d_in[1];

    const int E = in_sizes[1];
    const int d = in_sizes[0] / E;     // 64
    const int N = out_size / d - E;    // 50000

    float* mv = (float*)d_out;
    float* w  = (float*)d_out + (size_t)N * d;

    const int T = 256;

    if (d == 64 && N <= NCAP && E <= ECAP) {
        k_zero_cnt<<<(N + T) / T, T>>>(N);
        k_hist<<<(E + T - 1) / T, T>>>(dest, E);
        k_scan<<<1, 1024>>>(N);
        k_scatter<<<(E + T - 1) / T, T>>>(dest, E);
        int threads = N * 32;
        k_node64<<<(threads + T - 1) / T, T>>>(M, mv, w, N);
    } else {
        const int seg = N * d, total = E * d;
        unsigned* mv_u = (unsigned*)d_out;
        k_init_g<<<(seg + T - 1) / T, T>>>(mv_u, seg);
        k_max_g<<<(total + T - 1) / T, T>>>(M, dest, mv_u, total, d);
        k_dec_g<<<(seg + T - 1) / T, T>>>(mv_u, seg);
        k_denom_g<<<(total + T - 1) / T, T>>>(M, dest, mv, total, d);
        k_w_g<<<(total + T - 1) / T, T>>>(M, dest, mv, w, total, d);
    }
}